// round 8
// baseline (speedup 1.0000x reference)
#include <cuda_runtime.h>
#include <cuda_bf16.h>
#include <cfloat>

// Problem constants
#define BATCH 8
#define NT 1024
#define CH 512
#define HH 32
#define WW 32
#define NBOX 256
#define OS 7
#define KDIM (OS * OS * CH)      // 25088; K order: c*49 + (i*7+j)  (NATIVE conv_w order)
#define XELEMS (BATCH * NT * CH) // 4194304
#define OUTFEATS (NBOX * CH)     // 131072

// GEMM config
#define GTM 64
#define GTN 64
#define GTK 16
#define SPLITS 32
#define KCHUNK (KDIM / SPLITS)   // 784 = 16 * 49

// Device scratch (allocation-free rule: __device__ globals)
__device__ float g_pool[NBOX * KDIM];        // [k][c*49 + ij]
__device__ float g_partial[SPLITS * OUTFEATS];

// ---------------------------------------------------------------------------
// Kernel 1: passthrough copy of x into out[0 : XELEMS]
// ---------------------------------------------------------------------------
__global__ void copy_x_kernel(const float4* __restrict__ src, float4* __restrict__ dst) {
    int i = blockIdx.x * blockDim.x + threadIdx.x;
    dst[i] = src[i];
}

// ---------------------------------------------------------------------------
// Kernel 2: ROI max pool -> g_pool[k][c*49 + i*7 + j]
// One CTA per box (256), one thread per channel (512).
//
// CRITICAL: XLA's algebraic simplifier lowers `roi_len / 7` to
// `roi_len * fl(1/7)` (multiply by correctly-rounded reciprocal). For
// L in {3, 6, 9, 11} this makes the p=6 upper boundary ceil(7*bs) == L+1
// (one extra pixel line in the last bin), which IEEE division never does.
// We emulate that lowering LITERALLY with __fmul_rn so nvcc cannot
// re-rewrite it:
//   bs = fl(L * fl(1/7))
//   lo_p = clip(floor(fl(p*bs)) + start, 0, 32)
//   hi_p = clip(ceil (fl((p+1)*bs)) + start, 0, 32)
// ---------------------------------------------------------------------------
__global__ void roi_pool_kernel(const float* __restrict__ x, const float* __restrict__ boxes) {
    const int k = blockIdx.x;
    const int c = threadIdx.x;                 // 0..511
    const float* bx = boxes + k * 5;
    const int b = (int)bx[0];
    // jnp.round == round-half-to-even == rintf; *32 exact (power of two)
    const float x1 = rintf(bx[1] * 32.0f);
    const float y1 = rintf(bx[2] * 32.0f);
    const float x2 = rintf(bx[3] * 32.0f);
    const float y2 = rintf(bx[4] * 32.0f);
    const float rw = fmaxf(x2 - x1 + 1.0f, 1.0f);
    const float rh = fmaxf(y2 - y1 + 1.0f, 1.0f);
    const float INV7 = 1.0f / 7.0f;            // fl(1/7) = 0x3E124925, host-rounded
    const float bsw = __fmul_rn(rw, INV7);     // XLA reciprocal-multiply semantics
    const float bsh = __fmul_rn(rh, INV7);

    int hs[OS], he[OS], ws[OS], we[OS];
#pragma unroll
    for (int p = 0; p < OS; p++) {
        const float pf = (float)p;
        const float pf1 = (float)(p + 1);
        hs[p] = (int)fminf(fmaxf(floorf(__fmul_rn(pf, bsh)) + y1, 0.0f), 32.0f);
        he[p] = (int)fminf(fmaxf(ceilf(__fmul_rn(pf1, bsh)) + y1, 0.0f), 32.0f);
        ws[p] = (int)fminf(fmaxf(floorf(__fmul_rn(pf, bsw)) + x1, 0.0f), 32.0f);
        we[p] = (int)fminf(fmaxf(ceilf(__fmul_rn(pf1, bsw)) + x1, 0.0f), 32.0f);
    }

    const float* fb = x + (size_t)b * (NT * CH) + c;      // + (h*32+w)*512
    float* pb = g_pool + (size_t)k * KDIM + (size_t)c * (OS * OS);

#pragma unroll
    for (int i = 0; i < OS; i++) {
#pragma unroll
        for (int j = 0; j < OS; j++) {
            float m = -FLT_MAX;
            for (int h = hs[i]; h < he[i]; h++) {
                const float* rowp = fb + (size_t)(h << 5) * CH;
                for (int w = ws[j]; w < we[j]; w++) {
                    m = fmaxf(m, rowp[(size_t)w * CH]);
                }
            }
            // reference: where(pool <= NEG*0.5, 0, pool)
            pb[i * OS + j] = (m <= -0.5f * FLT_MAX) ? 0.0f : m;
        }
    }
}

// ---------------------------------------------------------------------------
// Kernel 3: split-K GEMM.  C[m,n] = sum_t A[m,t] * B[n,t]
// A = g_pool (256 x 25088, native K order), B = conv_w (512 x 25088, NATIVE
// flat layout — B[n][c*49+ij] == conv_w[n,c,i,j], no transpose needed, so
// the K pairing with A is correct by construction).
// 64x64 tile, 4x4 microtile, K-tile 16; grid (4, 8, 32).
// ---------------------------------------------------------------------------
__global__ void __launch_bounds__(256) gemm_splitk_kernel(const float* __restrict__ W) {
    __shared__ __align__(16) float As[GTK][GTM];
    __shared__ __align__(16) float Bs[GTK][GTN];

    const int m0 = blockIdx.x * GTM;
    const int n0 = blockIdx.y * GTN;
    const int kz0 = blockIdx.z * KCHUNK;

    const int lrow = threadIdx.x >> 2;        // 0..63
    const int lk   = (threadIdx.x & 3) * 4;   // 0,4,8,12
    const int tm = threadIdx.x >> 4;          // 0..15
    const int tn = threadIdx.x & 15;          // 0..15

    const float* Ap = g_pool + (size_t)(m0 + lrow) * KDIM + kz0 + lk;
    const float* Bp = W      + (size_t)(n0 + lrow) * KDIM + kz0 + lk;

    float acc[4][4];
#pragma unroll
    for (int i = 0; i < 4; i++)
#pragma unroll
        for (int j = 0; j < 4; j++) acc[i][j] = 0.0f;

    for (int kt = 0; kt < KCHUNK; kt += GTK) {
        float4 av = *(const float4*)(Ap + kt);
        float4 bv = *(const float4*)(Bp + kt);
        __syncthreads();
        As[lk + 0][lrow] = av.x; As[lk + 1][lrow] = av.y;
        As[lk + 2][lrow] = av.z; As[lk + 3][lrow] = av.w;
        Bs[lk + 0][lrow] = bv.x; Bs[lk + 1][lrow] = bv.y;
        Bs[lk + 2][lrow] = bv.z; Bs[lk + 3][lrow] = bv.w;
        __syncthreads();
#pragma unroll
        for (int kk = 0; kk < GTK; kk++) {
            const float4 a = *(const float4*)&As[kk][tm * 4];
            const float4 b = *(const float4*)&Bs[kk][tn * 4];
            acc[0][0] = fmaf(a.x, b.x, acc[0][0]);
            acc[0][1] = fmaf(a.x, b.y, acc[0][1]);
            acc[0][2] = fmaf(a.x, b.z, acc[0][2]);
            acc[0][3] = fmaf(a.x, b.w, acc[0][3]);
            acc[1][0] = fmaf(a.y, b.x, acc[1][0]);
            acc[1][1] = fmaf(a.y, b.y, acc[1][1]);
            acc[1][2] = fmaf(a.y, b.z, acc[1][2]);
            acc[1][3] = fmaf(a.y, b.w, acc[1][3]);
            acc[2][0] = fmaf(a.z, b.x, acc[2][0]);
            acc[2][1] = fmaf(a.z, b.y, acc[2][1]);
            acc[2][2] = fmaf(a.z, b.z, acc[2][2]);
            acc[2][3] = fmaf(a.z, b.w, acc[2][3]);
            acc[3][0] = fmaf(a.w, b.x, acc[3][0]);
            acc[3][1] = fmaf(a.w, b.y, acc[3][1]);
            acc[3][2] = fmaf(a.w, b.z, acc[3][2]);
            acc[3][3] = fmaf(a.w, b.w, acc[3][3]);
        }
    }

    float* dst = g_partial + (size_t)blockIdx.z * OUTFEATS;
#pragma unroll
    for (int r = 0; r < 4; r++) {
        const int m = m0 + tm * 4 + r;
        *(float4*)(dst + (size_t)m * CH + n0 + tn * 4) =
            make_float4(acc[r][0], acc[r][1], acc[r][2], acc[r][3]);
    }
}

// ---------------------------------------------------------------------------
// Kernel 4: reduce partials + bias -> out[XELEMS : XELEMS+OUTFEATS]
// box_feats flat layout: k*512 + o.
// ---------------------------------------------------------------------------
__global__ void reduce_kernel(const float* __restrict__ bias, float* __restrict__ out) {
    int idx = blockIdx.x * blockDim.x + threadIdx.x;
    if (idx >= OUTFEATS) return;
    float s = bias[idx & 511];
#pragma unroll
    for (int sp = 0; sp < SPLITS; sp++) s += g_partial[(size_t)sp * OUTFEATS + idx];
    out[XELEMS + idx] = s;
}

// ---------------------------------------------------------------------------
extern "C" void kernel_launch(void* const* d_in, const int* in_sizes, int n_in,
                              void* d_out, int out_size) {
    const float* x      = (const float*)d_in[0];
    const float* boxes  = (const float*)d_in[1];
    // d_in[2] = box_labels (unused)
    const float* conv_w = (const float*)d_in[3];
    const float* conv_b = (const float*)d_in[4];
    float* out = (float*)d_out;

    // 1) passthrough copy of x (verified exact)
    copy_x_kernel<<<XELEMS / 4 / 256, 256>>>((const float4*)x, (float4*)out);

    // 2) ROI pooling into native K order (XLA reciprocal-multiply bin semantics)
    roi_pool_kernel<<<NBOX, CH>>>(x, boxes);

    // 3) split-K GEMM straight against conv_w (no transpose)
    {
        dim3 grid(NBOX / GTM, CH / GTN, SPLITS);
        gemm_splitk_kernel<<<grid, 256>>>(conv_w);
    }

    // 4) reduce + bias
    reduce_kernel<<<(OUTFEATS + 255) / 256, 256>>>(conv_b, out);
}

// round 11
// speedup vs baseline: 2.6250x; 2.6250x over previous
#include <cuda_runtime.h>
#include <cuda_bf16.h>
#include <cfloat>
#include <cstdint>

// Problem constants
#define BATCH 8
#define NT 1024
#define CH 512
#define NBOX 256
#define OS 7
#define KDIM (OS * OS * CH)      // 25088; K order: c*49 + (i*7+j) (NATIVE conv_w order)
#define XELEMS (BATCH * NT * CH) // 4194304
#define OUTFEATS (NBOX * CH)     // 131072

// GEMM config (mma.sync path — base sm_103 target has NO tcgen05)
#define GM 128
#define GN 128
#define SPLITS 14
#define KCHUNK (KDIM / SPLITS)   // 1792
#define KST 16
#define NST (KCHUNK / KST)       // 112

// smem: per stage 4 tiles (Ahi,Alo,Bhi,Blo), each 128 rows x 24 bf16 (stride
// 24 = 48B -> ldmatrix conflict-free: banks 12L mod 32 all distinct)
#define RS_ELEM 24
#define RS_BYTES 48
#define TILE_BYTES (128 * RS_BYTES)      // 6144
#define OFF_AHI 0
#define OFF_ALO (TILE_BYTES)
#define OFF_BHI (2 * TILE_BYTES)
#define OFF_BLO (3 * TILE_BYTES)
#define STAGE_BYTES (4 * TILE_BYTES)     // 24576
#define GEMM_SMEM (2 * STAGE_BYTES)      // 49152 (fits default 48KB dyn smem)

// Device scratch (allocation-free rule: __device__ globals)
__device__ __align__(16) float g_pool[NBOX * KDIM];
__device__ __align__(16) float g_partial[SPLITS * OUTFEATS];

// ---------------------------------------------------------------------------
// helpers
// ---------------------------------------------------------------------------
__device__ __forceinline__ uint32_t smem_to_u32(const void* p) {
    uint32_t a;
    asm("{ .reg .u64 t; cvta.to.shared.u64 t, %1; cvt.u32.u64 %0, t; }" : "=r"(a) : "l"(p));
    return a;
}
__device__ __forceinline__ void ldsm_x4(uint32_t* r, uint32_t addr) {
    asm volatile("ldmatrix.sync.aligned.m8n8.x4.shared.b16 {%0,%1,%2,%3}, [%4];"
        : "=r"(r[0]), "=r"(r[1]), "=r"(r[2]), "=r"(r[3]) : "r"(addr));
}
__device__ __forceinline__ void ldsm_x2(uint32_t* r, uint32_t addr) {
    asm volatile("ldmatrix.sync.aligned.m8n8.x2.shared.b16 {%0,%1}, [%2];"
        : "=r"(r[0]), "=r"(r[1]) : "r"(addr));
}
__device__ __forceinline__ void mma_bf16(float* c, const uint32_t* a, const uint32_t* b) {
    asm volatile("mma.sync.aligned.m16n8k16.row.col.f32.bf16.bf16.f32 "
        "{%0,%1,%2,%3}, {%4,%5,%6,%7}, {%8,%9}, {%0,%1,%2,%3};"
        : "+f"(c[0]), "+f"(c[1]), "+f"(c[2]), "+f"(c[3])
        : "r"(a[0]), "r"(a[1]), "r"(a[2]), "r"(a[3]), "r"(b[0]), "r"(b[1]));
}
// fp32 -> bf16 hi + bf16 lo (exact two-term split, packed as bf16x2 words)
__device__ __forceinline__ void split_pack(float4 v, uint2& hi, uint2& lo) {
    __nv_bfloat16 h0 = __float2bfloat16_rn(v.x);
    __nv_bfloat16 h1 = __float2bfloat16_rn(v.y);
    __nv_bfloat16 h2 = __float2bfloat16_rn(v.z);
    __nv_bfloat16 h3 = __float2bfloat16_rn(v.w);
    float r0 = v.x - __bfloat162float(h0);
    float r1 = v.y - __bfloat162float(h1);
    float r2 = v.z - __bfloat162float(h2);
    float r3 = v.w - __bfloat162float(h3);
    __nv_bfloat162 hp0; hp0.x = h0; hp0.y = h1;
    __nv_bfloat162 hp1; hp1.x = h2; hp1.y = h3;
    __nv_bfloat162 lp0; lp0.x = __float2bfloat16_rn(r0); lp0.y = __float2bfloat16_rn(r1);
    __nv_bfloat162 lp1; lp1.x = __float2bfloat16_rn(r2); lp1.y = __float2bfloat16_rn(r3);
    hi.x = *reinterpret_cast<uint32_t*>(&hp0); hi.y = *reinterpret_cast<uint32_t*>(&hp1);
    lo.x = *reinterpret_cast<uint32_t*>(&lp0); lo.y = *reinterpret_cast<uint32_t*>(&lp1);
}

// ---------------------------------------------------------------------------
// Kernel 1: passthrough copy of x into out[0 : XELEMS]
// ---------------------------------------------------------------------------
__global__ void copy_x_kernel(const float4* __restrict__ src, float4* __restrict__ dst) {
    int i = blockIdx.x * blockDim.x + threadIdx.x;
    dst[i] = src[i];
}

// ---------------------------------------------------------------------------
// Kernel 2: ROI max pool -> g_pool[k][c*49 + i*7 + j]
// UNCHANGED from the passing R8 kernel (XLA reciprocal-multiply semantics).
// ---------------------------------------------------------------------------
__global__ void roi_pool_kernel(const float* __restrict__ x, const float* __restrict__ boxes) {
    const int k = blockIdx.x;
    const int c = threadIdx.x;
    const float* bx = boxes + k * 5;
    const int b = (int)bx[0];
    const float x1 = rintf(bx[1] * 32.0f);
    const float y1 = rintf(bx[2] * 32.0f);
    const float x2 = rintf(bx[3] * 32.0f);
    const float y2 = rintf(bx[4] * 32.0f);
    const float rw = fmaxf(x2 - x1 + 1.0f, 1.0f);
    const float rh = fmaxf(y2 - y1 + 1.0f, 1.0f);
    const float INV7 = 1.0f / 7.0f;
    const float bsw = __fmul_rn(rw, INV7);
    const float bsh = __fmul_rn(rh, INV7);

    int hs[OS], he[OS], ws[OS], we[OS];
#pragma unroll
    for (int p = 0; p < OS; p++) {
        const float pf = (float)p;
        const float pf1 = (float)(p + 1);
        hs[p] = (int)fminf(fmaxf(floorf(__fmul_rn(pf, bsh)) + y1, 0.0f), 32.0f);
        he[p] = (int)fminf(fmaxf(ceilf(__fmul_rn(pf1, bsh)) + y1, 0.0f), 32.0f);
        ws[p] = (int)fminf(fmaxf(floorf(__fmul_rn(pf, bsw)) + x1, 0.0f), 32.0f);
        we[p] = (int)fminf(fmaxf(ceilf(__fmul_rn(pf1, bsw)) + x1, 0.0f), 32.0f);
    }

    const float* fb = x + (size_t)b * (NT * CH) + c;
    float* pb = g_pool + (size_t)k * KDIM + (size_t)c * (OS * OS);

#pragma unroll
    for (int i = 0; i < OS; i++) {
#pragma unroll
        for (int j = 0; j < OS; j++) {
            float m = -FLT_MAX;
            for (int h = hs[i]; h < he[i]; h++) {
                const float* rowp = fb + (size_t)(h << 5) * CH;
                for (int w = ws[j]; w < we[j]; w++) {
                    m = fmaxf(m, rowp[(size_t)w * CH]);
                }
            }
            pb[i * OS + j] = (m <= -0.5f * FLT_MAX) ? 0.0f : m;
        }
    }
}

// ---------------------------------------------------------------------------
// Kernel 3: bf16-split GEMM on the tensor pipe via mma.sync (HMMA.16816).
// D[m,n] = sum_t A[m,t]*B[n,t];  A = g_pool, B = conv_w (native layout ->
// K pairing correct by construction). fp32 = hi + lo bf16; accumulate
// Ahi*Bhi + Ahi*Blo + Alo*Bhi in fp32 (err ~1e-5).
// Grid (2, 4, 14), 256 threads (8 warps: 2 m-blocks x 4 n-blocks; each warp
// 64x32). K in 112 double-buffered stages of 16.
// ---------------------------------------------------------------------------
__global__ void __launch_bounds__(256) gemm_mma_kernel(const float* __restrict__ W) {
    extern __shared__ char smem[];
    const uint32_t sb = smem_to_u32(smem);
    const int tid = threadIdx.x;
    const int wid = tid >> 5;
    const int lane = tid & 31;
    const int warp_m = wid & 1;          // 0..1 -> 64-row block
    const int warp_n = wid >> 1;         // 0..3 -> 32-col block

    const int m0 = blockIdx.x * GM;
    const int n0 = blockIdx.y * GN;
    const int kz = blockIdx.z * KCHUNK;

    // per-thread global load coords (2 float4 per matrix per stage)
    const int idx0 = tid, idx1 = tid + 256;       // over 512 float4 = 128x16
    const int r0 = idx0 >> 2, c0 = (idx0 & 3) << 2;
    const int r1 = idx1 >> 2, c1 = (idx1 & 3) << 2;
    const float* A0 = g_pool + (size_t)(m0 + r0) * KDIM + kz + c0;
    const float* A1 = g_pool + (size_t)(m0 + r1) * KDIM + kz + c1;
    const float* B0 = W + (size_t)(n0 + r0) * KDIM + kz + c0;
    const float* B1 = W + (size_t)(n0 + r1) * KDIM + kz + c1;
    const uint32_t st0 = (uint32_t)(r0 * RS_BYTES + c0 * 2);
    const uint32_t st1 = (uint32_t)(r1 * RS_BYTES + c1 * 2);

    // ldmatrix per-lane addresses (within a stage buffer)
    const uint32_t aoff = (uint32_t)((warp_m * 64 + (lane & 15)) * RS_BYTES + (lane >> 4) * 16);
    const uint32_t boff = (uint32_t)((warp_n * 32 + (lane & 7)) * RS_BYTES + ((lane >> 3) & 1) * 16);

    float acc[4][4][4];
#pragma unroll
    for (int mi = 0; mi < 4; mi++)
#pragma unroll
        for (int ni = 0; ni < 4; ni++)
#pragma unroll
            for (int q = 0; q < 4; q++) acc[mi][ni][q] = 0.0f;

    // preload stage 0 into buffer 0
    {
        float4 av0 = *(const float4*)A0;
        float4 av1 = *(const float4*)A1;
        float4 bv0 = *(const float4*)B0;
        float4 bv1 = *(const float4*)B1;
        uint2 hi, lo;
        split_pack(av0, hi, lo);
        *(uint2*)(smem + OFF_AHI + st0) = hi; *(uint2*)(smem + OFF_ALO + st0) = lo;
        split_pack(av1, hi, lo);
        *(uint2*)(smem + OFF_AHI + st1) = hi; *(uint2*)(smem + OFF_ALO + st1) = lo;
        split_pack(bv0, hi, lo);
        *(uint2*)(smem + OFF_BHI + st0) = hi; *(uint2*)(smem + OFF_BLO + st0) = lo;
        split_pack(bv1, hi, lo);
        *(uint2*)(smem + OFF_BHI + st1) = hi; *(uint2*)(smem + OFF_BLO + st1) = lo;
    }
    __syncthreads();

    for (int s = 0; s < NST; s++) {
        const uint32_t bufb = sb + (uint32_t)(s & 1) * STAGE_BYTES;
        char* nbuf = smem + ((s + 1) & 1) * STAGE_BYTES;

        // prefetch next stage from global (hide L2 latency under MMAs)
        float4 av0, av1, bv0, bv1;
        const bool more = (s + 1 < NST);
        if (more) {
            const int ko = (s + 1) * KST;
            av0 = *(const float4*)(A0 + ko);
            av1 = *(const float4*)(A1 + ko);
            bv0 = *(const float4*)(B0 + ko);
            bv1 = *(const float4*)(B1 + ko);
        }

        // load fragments
        uint32_t ahi[4][4], alo[4][4], bhi[4][2], blo[4][2];
#pragma unroll
        for (int mi = 0; mi < 4; mi++) {
            ldsm_x4(ahi[mi], bufb + OFF_AHI + aoff + mi * (16 * RS_BYTES));
            ldsm_x4(alo[mi], bufb + OFF_ALO + aoff + mi * (16 * RS_BYTES));
        }
#pragma unroll
        for (int ni = 0; ni < 4; ni++) {
            ldsm_x2(bhi[ni], bufb + OFF_BHI + boff + ni * (8 * RS_BYTES));
            ldsm_x2(blo[ni], bufb + OFF_BLO + boff + ni * (8 * RS_BYTES));
        }

        // 3-pass bf16-split MMAs
#pragma unroll
        for (int mi = 0; mi < 4; mi++)
#pragma unroll
            for (int ni = 0; ni < 4; ni++) {
                mma_bf16(acc[mi][ni], ahi[mi], bhi[ni]);
                mma_bf16(acc[mi][ni], ahi[mi], blo[ni]);
                mma_bf16(acc[mi][ni], alo[mi], bhi[ni]);
            }

        // store next stage into the other buffer
        if (more) {
            uint2 hi, lo;
            split_pack(av0, hi, lo);
            *(uint2*)(nbuf + OFF_AHI + st0) = hi; *(uint2*)(nbuf + OFF_ALO + st0) = lo;
            split_pack(av1, hi, lo);
            *(uint2*)(nbuf + OFF_AHI + st1) = hi; *(uint2*)(nbuf + OFF_ALO + st1) = lo;
            split_pack(bv0, hi, lo);
            *(uint2*)(nbuf + OFF_BHI + st0) = hi; *(uint2*)(nbuf + OFF_BLO + st0) = lo;
            split_pack(bv1, hi, lo);
            *(uint2*)(nbuf + OFF_BHI + st1) = hi; *(uint2*)(nbuf + OFF_BLO + st1) = lo;
        }
        __syncthreads();
    }

    // epilogue: C fragment layout -> g_partial[z][m][n]
    float* part = g_partial + (size_t)blockIdx.z * OUTFEATS;
    const int lr = lane >> 2, lc = (lane & 3) * 2;
#pragma unroll
    for (int mi = 0; mi < 4; mi++) {
        const int mrow = m0 + warp_m * 64 + mi * 16 + lr;
#pragma unroll
        for (int ni = 0; ni < 4; ni++) {
            const int ncol = n0 + warp_n * 32 + ni * 8 + lc;
            float* p = part + (size_t)mrow * CH + ncol;
            *(float2*)p = make_float2(acc[mi][ni][0], acc[mi][ni][1]);
            float* p2 = p + 8 * CH;
            *(float2*)p2 = make_float2(acc[mi][ni][2], acc[mi][ni][3]);
        }
    }
}

// ---------------------------------------------------------------------------
// Kernel 4: reduce partials + bias -> out[XELEMS : XELEMS+OUTFEATS]
// ---------------------------------------------------------------------------
__global__ void reduce_kernel(const float* __restrict__ bias, float* __restrict__ out) {
    int idx = blockIdx.x * blockDim.x + threadIdx.x;
    if (idx >= OUTFEATS) return;
    float s = bias[idx & 511];
#pragma unroll
    for (int sp = 0; sp < SPLITS; sp++) s += g_partial[(size_t)sp * OUTFEATS + idx];
    out[XELEMS + idx] = s;
}

// ---------------------------------------------------------------------------
extern "C" void kernel_launch(void* const* d_in, const int* in_sizes, int n_in,
                              void* d_out, int out_size) {
    const float* x      = (const float*)d_in[0];
    const float* boxes  = (const float*)d_in[1];
    const float* conv_w = (const float*)d_in[3];
    const float* conv_b = (const float*)d_in[4];
    float* out = (float*)d_out;

    copy_x_kernel<<<XELEMS / 4 / 256, 256>>>((const float4*)x, (float4*)out);

    roi_pool_kernel<<<NBOX, CH>>>(x, boxes);

    {
        dim3 grid(NBOX / GM, CH / GN, SPLITS);
        gemm_mma_kernel<<<grid, 256, GEMM_SMEM>>>(conv_w);
    }

    reduce_kernel<<<(OUTFEATS + 255) / 256, 256>>>(conv_b, out);
}